// round 1
// baseline (speedup 1.0000x reference)
#include <cuda_runtime.h>
#include <cuda_bf16.h>

// Computation collapses: reference hardcodes edge weights = 0, so the neighbor
// aggregation term h_N is identically zero and each "SAGE conv" is just
//   concat([h, 0]) @ W + b  ==  h @ W[0:64,:] + b
// Full model:  out = relu(h @ W1[0:64] + b1) @ W2[0:64] + b2
// src/dst/deg are irrelevant.

#define IN_F   64
#define HID_F  64
#define OUT_F  32
#define TPB    256

__global__ __launch_bounds__(TPB, 2)
void mlp_fused_kernel(const float* __restrict__ h,
                      const float* __restrict__ W1,   // (128, 64), rows 0..63 used
                      const float* __restrict__ b1,   // (64,)
                      const float* __restrict__ W2,   // (128, 32), rows 0..63 used
                      const float* __restrict__ b2,   // (32,)
                      float* __restrict__ out,        // (N, 32)
                      int N)
{
    __shared__ float sW1[IN_F * HID_F];    // 16 KB, sW1[i*64+j] = W1[i][j]
    __shared__ float sW2[HID_F * OUT_F];   // 8 KB,  sW2[j*32+o] = W2[j][o]
    __shared__ float sb1[HID_F];
    __shared__ float sb2[OUT_F];

    const int tid = threadIdx.x;

    // Stage weights (first 64 rows of each matrix are contiguous at the front).
    #pragma unroll
    for (int i = tid; i < (IN_F * HID_F) / 4; i += TPB)
        ((float4*)sW1)[i] = ((const float4*)W1)[i];
    #pragma unroll
    for (int i = tid; i < (HID_F * OUT_F) / 4; i += TPB)
        ((float4*)sW2)[i] = ((const float4*)W2)[i];
    if (tid < HID_F) sb1[tid] = b1[tid];
    if (tid < OUT_F) sb2[tid] = b2[tid];
    __syncthreads();

    const int n = blockIdx.x * TPB + tid;
    if (n >= N) return;

    // ---------------- Layer 1: hid = relu(h_row @ W1 + b1) ----------------
    float acc[HID_F];
    #pragma unroll
    for (int j = 0; j < HID_F; ++j) acc[j] = sb1[j];

    const float4* __restrict__ row = (const float4*)(h + (size_t)n * IN_F);

    #pragma unroll 2
    for (int i4 = 0; i4 < IN_F / 4; ++i4) {
        const float4 v = row[i4];
        const float xs[4] = {v.x, v.y, v.z, v.w};
        #pragma unroll
        for (int k = 0; k < 4; ++k) {
            const float xi = xs[k];
            const float4* __restrict__ wrow = (const float4*)(sW1 + (i4 * 4 + k) * HID_F);
            #pragma unroll
            for (int j4 = 0; j4 < HID_F / 4; ++j4) {
                const float4 w = wrow[j4];
                acc[j4 * 4 + 0] = fmaf(xi, w.x, acc[j4 * 4 + 0]);
                acc[j4 * 4 + 1] = fmaf(xi, w.y, acc[j4 * 4 + 1]);
                acc[j4 * 4 + 2] = fmaf(xi, w.z, acc[j4 * 4 + 2]);
                acc[j4 * 4 + 3] = fmaf(xi, w.w, acc[j4 * 4 + 3]);
            }
        }
    }

    #pragma unroll
    for (int j = 0; j < HID_F; ++j) acc[j] = fmaxf(acc[j], 0.0f);

    // ---------------- Layer 2: out = hid @ W2 + b2 (no relu) ----------------
    float o[OUT_F];
    #pragma unroll
    for (int c = 0; c < OUT_F; ++c) o[c] = sb2[c];

    #pragma unroll 4
    for (int j = 0; j < HID_F; ++j) {
        const float hj = acc[j];
        const float4* __restrict__ wrow = (const float4*)(sW2 + j * OUT_F);
        #pragma unroll
        for (int o4 = 0; o4 < OUT_F / 4; ++o4) {
            const float4 w = wrow[o4];
            o[o4 * 4 + 0] = fmaf(hj, w.x, o[o4 * 4 + 0]);
            o[o4 * 4 + 1] = fmaf(hj, w.y, o[o4 * 4 + 1]);
            o[o4 * 4 + 2] = fmaf(hj, w.z, o[o4 * 4 + 2]);
            o[o4 * 4 + 3] = fmaf(hj, w.w, o[o4 * 4 + 3]);
        }
    }

    float4* __restrict__ orow = (float4*)(out + (size_t)n * OUT_F);
    #pragma unroll
    for (int o4 = 0; o4 < OUT_F / 4; ++o4)
        orow[o4] = make_float4(o[o4 * 4 + 0], o[o4 * 4 + 1],
                               o[o4 * 4 + 2], o[o4 * 4 + 3]);
}

extern "C" void kernel_launch(void* const* d_in, const int* in_sizes, int n_in,
                              void* d_out, int out_size)
{
    // metadata order: h, W1, b1, W2, b2, src, dst
    const float* h  = (const float*)d_in[0];
    const float* W1 = (const float*)d_in[1];
    const float* b1 = (const float*)d_in[2];
    const float* W2 = (const float*)d_in[3];
    const float* b2 = (const float*)d_in[4];
    // d_in[5] (src) and d_in[6] (dst) are mathematically irrelevant (edge w == 0).

    float* out = (float*)d_out;
    const int N = in_sizes[0] / IN_F;   // 100000

    const int grid = (N + TPB - 1) / TPB;
    mlp_fused_kernel<<<grid, TPB>>>(h, W1, b1, W2, b2, out, N);
}

// round 2
// speedup vs baseline: 1.4647x; 1.4647x over previous
#include <cuda_runtime.h>
#include <cuda_bf16.h>

// Model collapses (edge weights hardcoded to 0):
//   out = relu(h @ W1[0:64,:] + b1) @ W2[0:64,:] + b2
// Pure 2-layer MLP over N=100000 rows. Register-tiled GEMM + packed f32x2 FMA.

#define TPB   256
#define ROWS  128        // rows per block
#define PITCH 68         // smem tile pitch in floats (bank-conflict-free, 16B-aligned rows)

__device__ __forceinline__ unsigned long long fma2(unsigned long long a,
                                                   unsigned long long b,
                                                   unsigned long long c) {
    unsigned long long d;
    asm("fma.rn.f32x2 %0, %1, %2, %3;" : "=l"(d) : "l"(a), "l"(b), "l"(c));
    return d;
}
__device__ __forceinline__ unsigned long long pack2(float lo, float hi) {
    unsigned long long d;
    asm("mov.b64 %0, {%1, %2};" : "=l"(d) : "f"(lo), "f"(hi));
    return d;
}
__device__ __forceinline__ void unpack2(unsigned long long v, float& lo, float& hi) {
    asm("mov.b64 {%0, %1}, %2;" : "=f"(lo), "=f"(hi) : "l"(v));
}

__global__ __launch_bounds__(TPB, 3)
void mlp_tiled_kernel(const float* __restrict__ h,
                      const float* __restrict__ W1,   // (128,64) rows 0..63 used
                      const float* __restrict__ b1,   // (64,)
                      const float* __restrict__ W2,   // (128,32) rows 0..63 used
                      const float* __restrict__ b2,   // (32,)
                      float* __restrict__ out,        // (N,32)
                      int N)
{
    __shared__ float sX[ROWS * PITCH];   // input tile, later reused for H1 tile (34816 B)
    __shared__ float sW1[64 * 64];       // 16 KB
    __shared__ float sW2[64 * 32];       // 8 KB
    __shared__ float sb1[64];
    __shared__ float sb2[32];

    const int tid  = threadIdx.x;
    const int row0 = blockIdx.x * ROWS;

    // ---- stage weights / biases ----
    #pragma unroll
    for (int i = tid; i < (64 * 64) / 4; i += TPB)
        ((float4*)sW1)[i] = ((const float4*)W1)[i];
    #pragma unroll
    for (int i = tid; i < (64 * 32) / 4; i += TPB)
        ((float4*)sW2)[i] = ((const float4*)W2)[i];
    if (tid < 64) sb1[tid] = b1[tid];
    if (tid < 32) sb2[tid] = b2[tid];

    // ---- stage input tile (zero-fill out-of-range rows) ----
    #pragma unroll
    for (int i = tid; i < ROWS * 16; i += TPB) {
        const int r  = i >> 4;
        const int c4 = i & 15;
        const int gr = row0 + r;
        float4 v = make_float4(0.f, 0.f, 0.f, 0.f);
        if (gr < N) v = ((const float4*)(h + (size_t)gr * 64))[c4];
        *((float4*)(sX + r * PITCH + c4 * 4)) = v;
    }
    __syncthreads();

    // thread tile mapping: 8 col-groups x 32 row-groups
    const int tx    = tid & 7;      // layer1: cols [tx*8, tx*8+8); layer2: cols [tx*4, tx*4+4)
    const int ty    = tid >> 3;     // rows [ty*4, ty*4+4)
    const int myrow = ty * 4;

    // =========== Layer 1: H1 = relu(X @ W1 + b1), thread tile 4x8 ===========
    unsigned long long acc[4][4];   // [row][col-pair]
    {
        const unsigned long long* bp = (const unsigned long long*)(sb1 + tx * 8);
        #pragma unroll
        for (int p = 0; p < 4; ++p) {
            const unsigned long long bv = bp[p];
            #pragma unroll
            for (int r = 0; r < 4; ++r) acc[r][p] = bv;
        }
    }

    #pragma unroll
    for (int k4 = 0; k4 < 16; ++k4) {
        float4 xr[4];
        #pragma unroll
        for (int r = 0; r < 4; ++r)
            xr[r] = *((const float4*)(sX + (myrow + r) * PITCH + k4 * 4));

        #pragma unroll
        for (int kk = 0; kk < 4; ++kk) {
            const int k = k4 * 4 + kk;
            const ulonglong2 w01 = *((const ulonglong2*)(sW1 + k * 64 + tx * 8));
            const ulonglong2 w23 = *((const ulonglong2*)(sW1 + k * 64 + tx * 8 + 4));
            const unsigned long long wp[4] = {w01.x, w01.y, w23.x, w23.y};
            #pragma unroll
            for (int r = 0; r < 4; ++r) {
                const float x = (kk == 0) ? xr[r].x : (kk == 1) ? xr[r].y
                              : (kk == 2) ? xr[r].z : xr[r].w;
                const unsigned long long x2 = pack2(x, x);
                #pragma unroll
                for (int p = 0; p < 4; ++p)
                    acc[r][p] = fma2(x2, wp[p], acc[r][p]);
            }
        }
    }

    // relu + writeback H1 tile into sX (all layer-1 reads are complete after sync)
    float h1v[4][8];
    #pragma unroll
    for (int r = 0; r < 4; ++r)
        #pragma unroll
        for (int p = 0; p < 4; ++p) {
            float lo, hi;
            unpack2(acc[r][p], lo, hi);
            h1v[r][2 * p]     = fmaxf(lo, 0.f);
            h1v[r][2 * p + 1] = fmaxf(hi, 0.f);
        }

    __syncthreads();
    #pragma unroll
    for (int r = 0; r < 4; ++r) {
        float* dst = sX + (myrow + r) * PITCH + tx * 8;
        *((float4*)dst)       = make_float4(h1v[r][0], h1v[r][1], h1v[r][2], h1v[r][3]);
        *((float4*)(dst + 4)) = make_float4(h1v[r][4], h1v[r][5], h1v[r][6], h1v[r][7]);
    }
    __syncthreads();

    // =========== Layer 2: out = H1 @ W2 + b2, thread tile 4x4 ===========
    unsigned long long acc2[4][2];
    {
        const unsigned long long* bp = (const unsigned long long*)(sb2 + tx * 4);
        #pragma unroll
        for (int p = 0; p < 2; ++p) {
            const unsigned long long bv = bp[p];
            #pragma unroll
            for (int r = 0; r < 4; ++r) acc2[r][p] = bv;
        }
    }

    #pragma unroll
    for (int k4 = 0; k4 < 16; ++k4) {
        float4 xr[4];
        #pragma unroll
        for (int r = 0; r < 4; ++r)
            xr[r] = *((const float4*)(sX + (myrow + r) * PITCH + k4 * 4));

        #pragma unroll
        for (int kk = 0; kk < 4; ++kk) {
            const int k = k4 * 4 + kk;
            const ulonglong2 w = *((const ulonglong2*)(sW2 + k * 32 + tx * 4));
            #pragma unroll
            for (int r = 0; r < 4; ++r) {
                const float x = (kk == 0) ? xr[r].x : (kk == 1) ? xr[r].y
                              : (kk == 2) ? xr[r].z : xr[r].w;
                const unsigned long long x2 = pack2(x, x);
                acc2[r][0] = fma2(x2, w.x, acc2[r][0]);
                acc2[r][1] = fma2(x2, w.y, acc2[r][1]);
            }
        }
    }

    // ---- store output (coalesced float4 per row, guarded) ----
    #pragma unroll
    for (int r = 0; r < 4; ++r) {
        const int gr = row0 + myrow + r;
        if (gr < N) {
            float a, b, c, d;
            unpack2(acc2[r][0], a, b);
            unpack2(acc2[r][1], c, d);
            *((float4*)(out + (size_t)gr * 32 + tx * 4)) = make_float4(a, b, c, d);
        }
    }
}

extern "C" void kernel_launch(void* const* d_in, const int* in_sizes, int n_in,
                              void* d_out, int out_size)
{
    // metadata order: h, W1, b1, W2, b2, src, dst (src/dst mathematically irrelevant)
    const float* h  = (const float*)d_in[0];
    const float* W1 = (const float*)d_in[1];
    const float* b1 = (const float*)d_in[2];
    const float* W2 = (const float*)d_in[3];
    const float* b2 = (const float*)d_in[4];

    float* out = (float*)d_out;
    const int N = in_sizes[0] / 64;   // 100000

    const int grid = (N + ROWS - 1) / ROWS;
    mlp_tiled_kernel<<<grid, TPB>>>(h, W1, b1, W2, b2, out, N);
}

// round 4
// speedup vs baseline: 3.0850x; 2.1062x over previous
#include <cuda_runtime.h>
#include <cuda_bf16.h>
#include <cstdint>

// out = relu(h @ W1[0:64,:] + b1) @ W2[0:64,:] + b2   (edge weights hardcoded 0)
// Warp-level bf16 split-precision HMMA (mma.sync m16n8k16), fp32 accumulate.
// D = Ahi*Bhi + Ahi*Blo + Alo*Bhi. Layer-1 C-frag == layer-2 A-frag layout,
// so activations never leave registers. No __syncthreads in the main loop.

#define TPB   256
#define NBLK  296

#define SWZ(o) ((uint32_t)(o) ^ ((((uint32_t)(o)) >> 3) & 0x70))

__device__ __forceinline__ uint32_t smem_u32(const void* p) {
    uint32_t a;
    asm("{ .reg .u64 t; cvta.to.shared.u64 t, %1; cvt.u32.u64 %0, t; }" : "=r"(a) : "l"(p));
    return a;
}

__device__ __forceinline__ void ldsm_x4_t(uint32_t& r0, uint32_t& r1, uint32_t& r2, uint32_t& r3,
                                          uint32_t addr) {
    asm volatile("ldmatrix.sync.aligned.m8n8.x4.trans.shared.b16 {%0,%1,%2,%3}, [%4];"
                 : "=r"(r0), "=r"(r1), "=r"(r2), "=r"(r3) : "r"(addr));
}

__device__ __forceinline__ void mma16816(float* c, uint32_t a0, uint32_t a1, uint32_t a2,
                                         uint32_t a3, uint32_t b0, uint32_t b1) {
    asm volatile(
        "mma.sync.aligned.m16n8k16.row.col.f32.bf16.bf16.f32 "
        "{%0,%1,%2,%3}, {%4,%5,%6,%7}, {%8,%9}, {%0,%1,%2,%3};"
        : "+f"(c[0]), "+f"(c[1]), "+f"(c[2]), "+f"(c[3])
        : "r"(a0), "r"(a1), "r"(a2), "r"(a3), "r"(b0), "r"(b1));
}

__device__ __forceinline__ void bsplit(float v, __nv_bfloat16& hi, __nv_bfloat16& lo) {
    hi = __float2bfloat16_rn(v);
    lo = __float2bfloat16_rn(v - __bfloat162float(hi));
}
__device__ __forceinline__ uint32_t packbf(__nv_bfloat16 a, __nv_bfloat16 b) {
    __nv_bfloat162 t = __halves2bfloat162(a, b);   // a = low half (even k), b = odd k
    uint32_t u; memcpy(&u, &t, 4); return u;
}
// split a float2 (even,odd k pair) into packed hi / lo bf16x2
__device__ __forceinline__ void split2(float2 v, uint32_t& hi, uint32_t& lo) {
    __nv_bfloat16 hx, lx, hy, ly;
    bsplit(v.x, hx, lx); bsplit(v.y, hy, ly);
    hi = packbf(hx, hy); lo = packbf(lx, ly);
}

__global__ __launch_bounds__(TPB, 2)
void mlp_hmma_kernel(const float* __restrict__ h,
                     const float* __restrict__ W1,   // (128,64), rows 0..63 used
                     const float* __restrict__ b1,   // (64,)
                     const float* __restrict__ W2,   // (128,32), rows 0..63 used
                     const float* __restrict__ b2,   // (32,)
                     float* __restrict__ out,        // (N,32)
                     int N, int nSlabs)
{
    // Weights only: [k][n] row-major bf16, 128B pitch, SW128-swizzled.
    __shared__ __align__(1024) uint8_t sW1h[64 * 128];
    __shared__ __align__(1024) uint8_t sW1l[64 * 128];
    __shared__ __align__(1024) uint8_t sW2h[64 * 128];   // 32 cols used, padded pitch
    __shared__ __align__(1024) uint8_t sW2l[64 * 128];

    const int tid = threadIdx.x;
    const int wid = tid >> 5;
    const int lid = tid & 31;

    for (int i = tid; i < 64 * 64; i += TPB) {            // W1: i = k*64 + n
        const int k = i >> 6, n = i & 63;
        __nv_bfloat16 hi, lo; bsplit(W1[i], hi, lo);
        const uint32_t sw = SWZ(k * 128 + n * 2);
        *(__nv_bfloat16*)(sW1h + sw) = hi;
        *(__nv_bfloat16*)(sW1l + sw) = lo;
    }
    for (int i = tid; i < 64 * 32; i += TPB) {            // W2: i = k*32 + n
        const int k = i >> 5, n = i & 31;
        __nv_bfloat16 hi, lo; bsplit(W2[i], hi, lo);
        const uint32_t sw = SWZ(k * 128 + n * 2);
        *(__nv_bfloat16*)(sW2h + sw) = hi;
        *(__nv_bfloat16*)(sW2l + sw) = lo;
    }
    __syncthreads();

    const uint32_t w1h = smem_u32(sW1h), w1l = smem_u32(sW1l);
    const uint32_t w2h = smem_u32(sW2h), w2l = smem_u32(sW2l);

    const int g = lid >> 2;        // row group 0..7
    const int t = lid & 3;         // col pair 0..3

    // per-lane ldmatrix source geometry: matrix idx lm (0..3), row lr (0..7)
    const int lm = lid >> 3, lr = lid & 7;
    const int kr = ((lm & 1) << 3) + lr;    // k row within 16-row k-step
    const int nc = (lm >> 1) << 3;          // n offset within 16-col n-group

    // biases held in registers, fragment-aligned
    float b1x[8], b1y[8], b2x[4], b2y[4];
    #pragma unroll
    for (int j = 0; j < 8; ++j) { b1x[j] = b1[8 * j + 2 * t]; b1y[j] = b1[8 * j + 2 * t + 1]; }
    #pragma unroll
    for (int j = 0; j < 4; ++j) { b2x[j] = b2[8 * j + 2 * t]; b2y[j] = b2[8 * j + 2 * t + 1]; }

    const int warpsTotal = gridDim.x * (TPB / 32);
    for (int slab = blockIdx.x * (TPB / 32) + wid; slab < nSlabs; slab += warpsTotal) {
        const int row0 = slab * 16;
        int rA = row0 + g, rB = row0 + g + 8;
        const bool okA = rA < N, okB = rB < N;
        if (rA >= N) rA = N - 1;               // clamp loads; stores guarded
        if (rB >= N) rB = N - 1;

        const float2* __restrict__ pA = (const float2*)(h + (size_t)rA * 64);
        const float2* __restrict__ pB = (const float2*)(h + (size_t)rB * 64);

        float c1[8][4];
        #pragma unroll
        for (int j = 0; j < 8; ++j)
            #pragma unroll
            for (int r = 0; r < 4; ++r) c1[j][r] = 0.f;

        // ---------------- Layer 1 ----------------
        #pragma unroll
        for (int s = 0; s < 4; ++s) {
            // A fragments straight from global (each element read once)
            uint32_t ah[4], al[4];
            split2(pA[8 * s + t],     ah[0], al[0]);   // rows g,   k 16s+2t
            split2(pB[8 * s + t],     ah[1], al[1]);   // rows g+8
            split2(pA[8 * s + 4 + t], ah[2], al[2]);   // rows g,   k 16s+8+2t
            split2(pB[8 * s + 4 + t], ah[3], al[3]);

            #pragma unroll
            for (int jj = 0; jj < 4; ++jj) {           // n-groups of 16 cols
                const uint32_t off = SWZ((16 * s + kr) * 128 + (16 * jj + nc) * 2);
                uint32_t bh0, bh1, bh2, bh3, bl0, bl1, bl2, bl3;
                ldsm_x4_t(bh0, bh1, bh2, bh3, w1h + off);
                ldsm_x4_t(bl0, bl1, bl2, bl3, w1l + off);
                mma16816(c1[2 * jj],     ah[0], ah[1], ah[2], ah[3], bh0, bh1);
                mma16816(c1[2 * jj],     ah[0], ah[1], ah[2], ah[3], bl0, bl1);
                mma16816(c1[2 * jj],     al[0], al[1], al[2], al[3], bh0, bh1);
                mma16816(c1[2 * jj + 1], ah[0], ah[1], ah[2], ah[3], bh2, bh3);
                mma16816(c1[2 * jj + 1], ah[0], ah[1], ah[2], ah[3], bl2, bl3);
                mma16816(c1[2 * jj + 1], al[0], al[1], al[2], al[3], bh2, bh3);
            }
        }

        // ---- epilogue 1: bias + relu + split; C-frag(ntile j) == A-frag(kstep j/2) ----
        uint32_t a2h[4][4], a2l[4][4];
        #pragma unroll
        for (int j = 0; j < 8; ++j) {
            const float x0 = fmaxf(c1[j][0] + b1x[j], 0.f);
            const float y0 = fmaxf(c1[j][1] + b1y[j], 0.f);
            const float x1 = fmaxf(c1[j][2] + b1x[j], 0.f);
            const float y1 = fmaxf(c1[j][3] + b1y[j], 0.f);
            const int s = j >> 1;
            const int o = (j & 1) << 1;                // even ntile -> a0,a1; odd -> a2,a3
            split2(make_float2(x0, y0), a2h[s][o],     a2l[s][o]);
            split2(make_float2(x1, y1), a2h[s][o + 1], a2l[s][o + 1]);
        }

        // ---------------- Layer 2 ----------------
        float c2[4][4];
        #pragma unroll
        for (int j = 0; j < 4; ++j)
            #pragma unroll
            for (int r = 0; r < 4; ++r) c2[j][r] = 0.f;

        #pragma unroll
        for (int s = 0; s < 4; ++s) {
            #pragma unroll
            for (int jj = 0; jj < 2; ++jj) {
                const uint32_t off = SWZ((16 * s + kr) * 128 + (16 * jj + nc) * 2);
                uint32_t bh0, bh1, bh2, bh3, bl0, bl1, bl2, bl3;
                ldsm_x4_t(bh0, bh1, bh2, bh3, w2h + off);
                ldsm_x4_t(bl0, bl1, bl2, bl3, w2l + off);
                mma16816(c2[2 * jj],     a2h[s][0], a2h[s][1], a2h[s][2], a2h[s][3], bh0, bh1);
                mma16816(c2[2 * jj],     a2h[s][0], a2h[s][1], a2h[s][2], a2h[s][3], bl0, bl1);
                mma16816(c2[2 * jj],     a2l[s][0], a2l[s][1], a2l[s][2], a2l[s][3], bh0, bh1);
                mma16816(c2[2 * jj + 1], a2h[s][0], a2h[s][1], a2h[s][2], a2h[s][3], bh2, bh3);
                mma16816(c2[2 * jj + 1], a2h[s][0], a2h[s][1], a2h[s][2], a2h[s][3], bl2, bl3);
                mma16816(c2[2 * jj + 1], a2l[s][0], a2l[s][1], a2l[s][2], a2l[s][3], bh2, bh3);
            }
        }

        // ---- epilogue 2: bias + store (float2, coalesced) ----
        #pragma unroll
        for (int j = 0; j < 4; ++j) {
            if (okA)
                *(float2*)(out + (size_t)(row0 + g) * 32 + 8 * j + 2 * t) =
                    make_float2(c2[j][0] + b2x[j], c2[j][1] + b2y[j]);
            if (okB)
                *(float2*)(out + (size_t)(row0 + g + 8) * 32 + 8 * j + 2 * t) =
                    make_float2(c2[j][2] + b2x[j], c2[j][3] + b2y[j]);
        }
    }
}

extern "C" void kernel_launch(void* const* d_in, const int* in_sizes, int n_in,
                              void* d_out, int out_size)
{
    const float* h  = (const float*)d_in[0];
    const float* W1 = (const float*)d_in[1];
    const float* b1 = (const float*)d_in[2];
    const float* W2 = (const float*)d_in[3];
    const float* b2 = (const float*)d_in[4];
    float* out = (float*)d_out;

    const int N = in_sizes[0] / 64;              // 100000
    const int nSlabs = (N + 15) / 16;            // 6250
    const int maxBlocks = (nSlabs + (TPB / 32) - 1) / (TPB / 32);
    const int grid = maxBlocks < NBLK ? maxBlocks : NBLK;

    mlp_hmma_kernel<<<grid, TPB>>>(h, W1, b1, W2, b2, out, N, nSlabs);
}

// round 5
// speedup vs baseline: 3.2801x; 1.0633x over previous
#include <cuda_runtime.h>
#include <cuda_bf16.h>
#include <cstdint>

// out = relu(h @ W1[0:64,:] + b1) @ W2[0:64,:] + b2   (edge weights hardcoded 0)
// Warp-level bf16 split-precision HMMA (mma.sync m16n8k16), fp32 accumulate.
// D = Ahi*Bhi + Ahi*Blo + Alo*Bhi. Layer-1 C-frag == layer-2 A-frag layout,
// so activations never leave registers. Biases in smem; packed bf16x2 splits.

#define TPB   256
#define NBLK  444   // 3 CTAs/SM * 148 SMs = one full wave ceiling

#define SWZ(o) ((uint32_t)(o) ^ ((((uint32_t)(o)) >> 3) & 0x70))

__device__ __forceinline__ uint32_t smem_u32(const void* p) {
    uint32_t a;
    asm("{ .reg .u64 t; cvta.to.shared.u64 t, %1; cvt.u32.u64 %0, t; }" : "=r"(a) : "l"(p));
    return a;
}

__device__ __forceinline__ void ldsm_x4_t(uint32_t& r0, uint32_t& r1, uint32_t& r2, uint32_t& r3,
                                          uint32_t addr) {
    asm volatile("ldmatrix.sync.aligned.m8n8.x4.trans.shared.b16 {%0,%1,%2,%3}, [%4];"
                 : "=r"(r0), "=r"(r1), "=r"(r2), "=r"(r3) : "r"(addr));
}

__device__ __forceinline__ void mma16816(float* c, uint32_t a0, uint32_t a1, uint32_t a2,
                                         uint32_t a3, uint32_t b0, uint32_t b1) {
    asm volatile(
        "mma.sync.aligned.m16n8k16.row.col.f32.bf16.bf16.f32 "
        "{%0,%1,%2,%3}, {%4,%5,%6,%7}, {%8,%9}, {%0,%1,%2,%3};"
        : "+f"(c[0]), "+f"(c[1]), "+f"(c[2]), "+f"(c[3])
        : "r"(a0), "r"(a1), "r"(a2), "r"(a3), "r"(b0), "r"(b1));
}

__device__ __forceinline__ void bsplit(float v, __nv_bfloat16& hi, __nv_bfloat16& lo) {
    hi = __float2bfloat16_rn(v);
    lo = __float2bfloat16_rn(v - __bfloat162float(hi));
}

// split float2 {even k, odd k} -> packed hi bf16x2 / lo bf16x2 (6 instrs).
// lo residual f - bf16(f) is exact in fp32, so this matches the scalar path bit-for-bit.
__device__ __forceinline__ void split2(float2 v, uint32_t& hi, uint32_t& lo) {
    uint32_t hp;
    asm("cvt.rn.bf16x2.f32 %0, %1, %2;" : "=r"(hp) : "f"(v.y), "f"(v.x));  // lo half = v.x
    const float h0 = __uint_as_float(hp << 16);
    const float h1 = __uint_as_float(hp & 0xFFFF0000u);
    const float l0 = v.x - h0;
    const float l1 = v.y - h1;
    uint32_t lp;
    asm("cvt.rn.bf16x2.f32 %0, %1, %2;" : "=r"(lp) : "f"(l1), "f"(l0));
    hi = hp; lo = lp;
}

__global__ __launch_bounds__(TPB, 3)
void mlp_hmma_kernel(const float* __restrict__ h,
                     const float* __restrict__ W1,   // (128,64), rows 0..63 used
                     const float* __restrict__ b1,   // (64,)
                     const float* __restrict__ W2,   // (128,32), rows 0..63 used
                     const float* __restrict__ b2,   // (32,)
                     float* __restrict__ out,        // (N,32)
                     int N, int nSlabs)
{
    // Weights: [k][n] row-major bf16, 128B pitch, SW128-swizzled. Biases fp32.
    __shared__ __align__(1024) uint8_t sW1h[64 * 128];
    __shared__ __align__(1024) uint8_t sW1l[64 * 128];
    __shared__ __align__(1024) uint8_t sW2h[64 * 128];   // 32 cols used, padded pitch
    __shared__ __align__(1024) uint8_t sW2l[64 * 128];
    __shared__ float sb1[64];
    __shared__ float sb2[32];

    const int tid = threadIdx.x;
    const int wid = tid >> 5;
    const int lid = tid & 31;

    for (int i = tid; i < 64 * 64; i += TPB) {            // W1: i = k*64 + n
        const int k = i >> 6, n = i & 63;
        __nv_bfloat16 hi, lo; bsplit(W1[i], hi, lo);
        const uint32_t sw = SWZ(k * 128 + n * 2);
        *(__nv_bfloat16*)(sW1h + sw) = hi;
        *(__nv_bfloat16*)(sW1l + sw) = lo;
    }
    for (int i = tid; i < 64 * 32; i += TPB) {            // W2: i = k*32 + n
        const int k = i >> 5, n = i & 31;
        __nv_bfloat16 hi, lo; bsplit(W2[i], hi, lo);
        const uint32_t sw = SWZ(k * 128 + n * 2);
        *(__nv_bfloat16*)(sW2h + sw) = hi;
        *(__nv_bfloat16*)(sW2l + sw) = lo;
    }
    if (tid < 64) sb1[tid] = b1[tid];
    if (tid < 32) sb2[tid] = b2[tid];
    __syncthreads();

    const uint32_t w1h = smem_u32(sW1h), w1l = smem_u32(sW1l);
    const uint32_t w2h = smem_u32(sW2h), w2l = smem_u32(sW2l);

    const int g = lid >> 2;        // row group 0..7
    const int t = lid & 3;         // col pair 0..3

    // per-lane ldmatrix source geometry: matrix idx lm (0..3), row lr (0..7)
    const int lm = lid >> 3, lr = lid & 7;
    const int kr = ((lm & 1) << 3) + lr;    // k row within 16-row k-step
    const int nc = (lm >> 1) << 3;          // n offset within 16-col n-group

    const int warpsTotal = gridDim.x * (TPB / 32);
    for (int slab = blockIdx.x * (TPB / 32) + wid; slab < nSlabs; slab += warpsTotal) {
        const int row0 = slab * 16;
        int rA = row0 + g, rB = row0 + g + 8;
        const bool okA = rA < N, okB = rB < N;
        if (rA >= N) rA = N - 1;               // clamp loads; stores guarded
        if (rB >= N) rB = N - 1;

        const float2* __restrict__ pA = (const float2*)(h + (size_t)rA * 64);
        const float2* __restrict__ pB = (const float2*)(h + (size_t)rB * 64);

        float c1[8][4];
        #pragma unroll
        for (int j = 0; j < 8; ++j)
            #pragma unroll
            for (int r = 0; r < 4; ++r) c1[j][r] = 0.f;

        // ---------------- Layer 1 ----------------
        #pragma unroll
        for (int s = 0; s < 4; ++s) {
            // A fragments straight from global (each element read once)
            uint32_t ah[4], al[4];
            split2(pA[8 * s + t],     ah[0], al[0]);   // rows g,   k 16s+2t
            split2(pB[8 * s + t],     ah[1], al[1]);   // rows g+8
            split2(pA[8 * s + 4 + t], ah[2], al[2]);   // rows g,   k 16s+8+2t
            split2(pB[8 * s + 4 + t], ah[3], al[3]);

            #pragma unroll
            for (int jj = 0; jj < 4; ++jj) {           // n-groups of 16 cols
                const uint32_t off = SWZ((16 * s + kr) * 128 + (16 * jj + nc) * 2);
                uint32_t bh0, bh1, bh2, bh3, bl0, bl1, bl2, bl3;
                ldsm_x4_t(bh0, bh1, bh2, bh3, w1h + off);
                ldsm_x4_t(bl0, bl1, bl2, bl3, w1l + off);
                mma16816(c1[2 * jj],     ah[0], ah[1], ah[2], ah[3], bh0, bh1);
                mma16816(c1[2 * jj],     ah[0], ah[1], ah[2], ah[3], bl0, bl1);
                mma16816(c1[2 * jj],     al[0], al[1], al[2], al[3], bh0, bh1);
                mma16816(c1[2 * jj + 1], ah[0], ah[1], ah[2], ah[3], bh2, bh3);
                mma16816(c1[2 * jj + 1], ah[0], ah[1], ah[2], ah[3], bl2, bl3);
                mma16816(c1[2 * jj + 1], al[0], al[1], al[2], al[3], bh2, bh3);
            }
        }

        // ---- epilogue 1: bias + relu + split; C-frag(ntile j) == A-frag(kstep j/2) ----
        uint32_t a2h[4][4], a2l[4][4];
        #pragma unroll
        for (int j = 0; j < 8; ++j) {
            const float2 bj = *(const float2*)(sb1 + 8 * j + 2 * t);
            const float x0 = fmaxf(c1[j][0] + bj.x, 0.f);
            const float y0 = fmaxf(c1[j][1] + bj.y, 0.f);
            const float x1 = fmaxf(c1[j][2] + bj.x, 0.f);
            const float y1 = fmaxf(c1[j][3] + bj.y, 0.f);
            const int s = j >> 1;
            const int o = (j & 1) << 1;                // even ntile -> a0,a1; odd -> a2,a3
            split2(make_float2(x0, y0), a2h[s][o],     a2l[s][o]);
            split2(make_float2(x1, y1), a2h[s][o + 1], a2l[s][o + 1]);
        }

        // ---------------- Layer 2 ----------------
        float c2[4][4];
        #pragma unroll
        for (int j = 0; j < 4; ++j)
            #pragma unroll
            for (int r = 0; r < 4; ++r) c2[j][r] = 0.f;

        #pragma unroll
        for (int s = 0; s < 4; ++s) {
            #pragma unroll
            for (int jj = 0; jj < 2; ++jj) {
                const uint32_t off = SWZ((16 * s + kr) * 128 + (16 * jj + nc) * 2);
                uint32_t bh0, bh1, bh2, bh3, bl0, bl1, bl2, bl3;
                ldsm_x4_t(bh0, bh1, bh2, bh3, w2h + off);
                ldsm_x4_t(bl0, bl1, bl2, bl3, w2l + off);
                mma16816(c2[2 * jj],     a2h[s][0], a2h[s][1], a2h[s][2], a2h[s][3], bh0, bh1);
                mma16816(c2[2 * jj],     a2h[s][0], a2h[s][1], a2h[s][2], a2h[s][3], bl0, bl1);
                mma16816(c2[2 * jj],     a2l[s][0], a2l[s][1], a2l[s][2], a2l[s][3], bh0, bh1);
                mma16816(c2[2 * jj + 1], a2h[s][0], a2h[s][1], a2h[s][2], a2h[s][3], bh2, bh3);
                mma16816(c2[2 * jj + 1], a2h[s][0], a2h[s][1], a2h[s][2], a2h[s][3], bl2, bl3);
                mma16816(c2[2 * jj + 1], a2l[s][0], a2l[s][1], a2l[s][2], a2l[s][3], bh2, bh3);
            }
        }

        // ---- epilogue 2: bias + store (float2, coalesced) ----
        #pragma unroll
        for (int j = 0; j < 4; ++j) {
            const float2 bj = *(const float2*)(sb2 + 8 * j + 2 * t);
            if (okA)
                *(float2*)(out + (size_t)(row0 + g) * 32 + 8 * j + 2 * t) =
                    make_float2(c2[j][0] + bj.x, c2[j][1] + bj.y);
            if (okB)
                *(float2*)(out + (size_t)(row0 + g + 8) * 32 + 8 * j + 2 * t) =
                    make_float2(c2[j][2] + bj.x, c2[j][3] + bj.y);
        }
    }
}

extern "C" void kernel_launch(void* const* d_in, const int* in_sizes, int n_in,
                              void* d_out, int out_size)
{
    const float* h  = (const float*)d_in[0];
    const float* W1 = (const float*)d_in[1];
    const float* b1 = (const float*)d_in[2];
    const float* W2 = (const float*)d_in[3];
    const float* b2 = (const float*)d_in[4];
    float* out = (float*)d_out;

    const int N = in_sizes[0] / 64;              // 100000
    const int nSlabs = (N + 15) / 16;            // 6250

    // ~2 slabs per warp, balanced; capped at one full wave (3 CTAs/SM).
    int grid = (nSlabs + 2 * (TPB / 32) - 1) / (2 * (TPB / 32));
    if (grid > NBLK) grid = NBLK;
    if (grid < 1) grid = 1;

    mlp_hmma_kernel<<<grid, TPB>>>(h, W1, b1, W2, b2, out, N, nSlabs);
}